// round 2
// baseline (speedup 1.0000x reference)
#include <cuda_runtime.h>
#include <cuda_bf16.h>
#include <math.h>

#define NN 100000
#define EE 1600000
#define DH 128
#define GG 64
#define CC 10

// ---------------- scratch (static device arrays; allocation is forbidden) ----
__device__ float g_t[NN * DH];       // t = h + agg  (GEMM1 input)
__device__ float g_hidden[NN * DH];  // relu(t@w1+b1)
__device__ float g_u[NN * DH];       // hidden@w2+b2 (conv output)
__device__ float g_h[NN * DH];       // activated/normalized h for next layer
__device__ int   g_counts[NN];
__device__ int   g_rowptr[NN + 1];
__device__ int   g_cur[NN];
__device__ int   g_csr_src[EE];
__device__ int   g_gstart[GG + 1];
__device__ float g_pool[GG * DH];

// ---------------- small helpers --------------------------------------------
__device__ __forceinline__ void fma2(unsigned long long& d,
                                     unsigned long long a,
                                     unsigned long long b) {
    asm("fma.rn.f32x2 %0, %1, %2, %0;" : "+l"(d) : "l"(a), "l"(b));
}
__device__ __forceinline__ unsigned long long pack2(float v) {
    unsigned long long r;
    asm("mov.b64 %0, {%1, %1};" : "=l"(r) : "f"(v));
    return r;
}
__device__ __forceinline__ void unpack2(unsigned long long v, float& lo, float& hi) {
    asm("mov.b64 {%0, %1}, %2;" : "=f"(lo), "=f"(hi) : "l"(v));
}

// ---------------- CSR build -------------------------------------------------
__global__ void zero_counts_pool() {
    int i = blockIdx.x * blockDim.x + threadIdx.x;
    if (i < NN) g_counts[i] = 0;
    if (i < GG * DH) g_pool[i] = 0.0f;
}

__global__ void count_edges(const int* __restrict__ dst) {
    int e = blockIdx.x * blockDim.x + threadIdx.x;
    if (e < EE) atomicAdd(&g_counts[dst[e]], 1);
}

__global__ void scan_rowptr() {
    __shared__ int warp_sums[32];
    __shared__ int s_carry;
    int tid = threadIdx.x;
    int lane = tid & 31, w = tid >> 5;
    if (tid == 0) s_carry = 0;
    __syncthreads();
    for (int base = 0; base < NN; base += 1024) {
        int i = base + tid;
        int v = (i < NN) ? g_counts[i] : 0;
        int incl = v;
        #pragma unroll
        for (int o = 1; o < 32; o <<= 1) {
            int t = __shfl_up_sync(0xffffffffu, incl, o);
            if (lane >= o) incl += t;
        }
        if (lane == 31) warp_sums[w] = incl;
        __syncthreads();
        if (w == 0) {
            int s = warp_sums[lane];
            #pragma unroll
            for (int o = 1; o < 32; o <<= 1) {
                int t = __shfl_up_sync(0xffffffffu, s, o);
                if (lane >= o) s += t;
            }
            warp_sums[lane] = s;
        }
        __syncthreads();
        int woff = (w > 0) ? warp_sums[w - 1] : 0;
        int excl = s_carry + woff + incl - v;
        if (i < NN) { g_rowptr[i] = excl; g_cur[i] = excl; }
        __syncthreads();            // everyone has consumed s_carry/warp_sums
        if (tid == 0) s_carry += warp_sums[31];
        __syncthreads();
    }
    if (threadIdx.x == 0) g_rowptr[NN] = s_carry;
}

__global__ void fill_csr(const int* __restrict__ src, const int* __restrict__ dst) {
    int e = blockIdx.x * blockDim.x + threadIdx.x;
    if (e < EE) {
        int p = atomicAdd(&g_cur[dst[e]], 1);
        g_csr_src[p] = src[e];
    }
}

__global__ void graph_bounds(const int* __restrict__ batch) {
    int g = threadIdx.x;
    if (g > GG) return;
    int lo = 0, hi = NN;
    while (lo < hi) {
        int mid = (lo + hi) >> 1;
        if (batch[mid] < g) lo = mid + 1; else hi = mid;
    }
    g_gstart[g] = lo;
}

// ---------------- gather:  t[n] = h[n] + sum_{src in CSR(n)} h[src] ---------
// FIRST=true reads from the kernel argument (x); otherwise from g_h.
template <bool FIRST>
__global__ void gather_kernel(const float* __restrict__ xin) {
    const float* __restrict__ h = FIRST ? xin : (const float*)g_h;
    int warp = threadIdx.x >> 5, lane = threadIdx.x & 31;
    int n = blockIdx.x * 8 + warp;
    if (n >= NN) return;
    int off = lane * 4;
    float4 acc = *(const float4*)&h[(size_t)n * DH + off];
    int p = g_rowptr[n], e = g_rowptr[n + 1];
    for (; p + 4 <= e; p += 4) {
        int s0 = g_csr_src[p], s1 = g_csr_src[p + 1];
        int s2 = g_csr_src[p + 2], s3 = g_csr_src[p + 3];
        float4 v0 = *(const float4*)&h[(size_t)s0 * DH + off];
        float4 v1 = *(const float4*)&h[(size_t)s1 * DH + off];
        float4 v2 = *(const float4*)&h[(size_t)s2 * DH + off];
        float4 v3 = *(const float4*)&h[(size_t)s3 * DH + off];
        acc.x += v0.x + v1.x + v2.x + v3.x;
        acc.y += v0.y + v1.y + v2.y + v3.y;
        acc.z += v0.z + v1.z + v2.z + v3.z;
        acc.w += v0.w + v1.w + v2.w + v3.w;
    }
    for (; p < e; ++p) {
        int s = g_csr_src[p];
        float4 v = *(const float4*)&h[(size_t)s * DH + off];
        acc.x += v.x; acc.y += v.y; acc.z += v.z; acc.w += v.w;
    }
    *(float4*)&g_t[(size_t)n * DH + off] = acc;
}

// ---------------- GEMM:  C[n,f] = (relu?)(sum_k A[n,k] W[k,f] + bias[f]) ----
// PHASE 0: A=g_t, C=g_hidden, relu.   PHASE 1: A=g_hidden, C=g_u, no relu.
// BM=64, BN=128, BK=32, 256 threads; packed f32x2 FMA (2 cols per 64-bit reg).
template <int PHASE>
__global__ void gemm128(const float* __restrict__ W,
                        const float* __restrict__ bias) {
    const float* __restrict__ A = (PHASE == 0) ? (const float*)g_t : (const float*)g_hidden;
    float* __restrict__ C       = (PHASE == 0) ? g_hidden : g_u;
    __shared__ float As[64][33];
    __shared__ float Bs[32][132];
    int tid = threadIdx.x;
    int tx = tid & 15;      // col group: cols [tx*8, tx*8+8)
    int ty = tid >> 4;      // row group: rows [ty*4, ty*4+4)
    int rowBase = blockIdx.x * 64;

    unsigned long long acc[4][4];
    #pragma unroll
    for (int i = 0; i < 4; i++)
        #pragma unroll
        for (int j = 0; j < 4; j++) acc[i][j] = 0ull;

    for (int kk = 0; kk < 128; kk += 32) {
        // load A chunk (64x32), guarded
        #pragma unroll
        for (int i = 0; i < 2; i++) {
            int e = tid * 8 + i * 4;
            int r = e >> 5, c = e & 31;
            float4 v = make_float4(0.f, 0.f, 0.f, 0.f);
            if (rowBase + r < NN)
                v = *(const float4*)&A[(size_t)(rowBase + r) * DH + kk + c];
            As[r][c] = v.x; As[r][c + 1] = v.y; As[r][c + 2] = v.z; As[r][c + 3] = v.w;
        }
        // load W chunk (32x128)
        #pragma unroll
        for (int i = 0; i < 4; i++) {
            int e = tid * 16 + i * 4;
            int r = e >> 7, c = e & 127;
            float4 v = *(const float4*)&W[(size_t)(kk + r) * DH + c];
            *(float4*)&Bs[r][c] = v;
        }
        __syncthreads();
        #pragma unroll 8
        for (int k = 0; k < 32; k++) {
            const unsigned long long* bp =
                (const unsigned long long*)&Bs[k][tx * 8];
            unsigned long long b0 = bp[0], b1 = bp[1], b2 = bp[2], b3 = bp[3];
            #pragma unroll
            for (int i = 0; i < 4; i++) {
                unsigned long long ap = pack2(As[ty * 4 + i][k]);
                fma2(acc[i][0], ap, b0);
                fma2(acc[i][1], ap, b1);
                fma2(acc[i][2], ap, b2);
                fma2(acc[i][3], ap, b3);
            }
        }
        __syncthreads();
    }
    // epilogue
    #pragma unroll
    for (int i = 0; i < 4; i++) {
        int r = rowBase + ty * 4 + i;
        if (r >= NN) continue;
        #pragma unroll
        for (int j = 0; j < 4; j++) {
            float lo, hi;
            unpack2(acc[i][j], lo, hi);
            int c = tx * 8 + j * 2;
            lo += bias[c];
            hi += bias[c + 1];
            if (PHASE == 0) { lo = fmaxf(lo, 0.f); hi = fmaxf(hi, 0.f); }
            C[(size_t)r * DH + c] = lo;
            C[(size_t)r * DH + c + 1] = hi;
        }
    }
}

// ---------------- epilogues -------------------------------------------------
// layers 0/1: h = LN(relu(u))
__global__ void epi_ln(const float* __restrict__ ln_g, const float* __restrict__ ln_b) {
    int warp = threadIdx.x >> 5, lane = threadIdx.x & 31;
    int n = blockIdx.x * 8 + warp;
    if (n >= NN) return;
    int off = lane * 4;
    float4 v = *(const float4*)&g_u[(size_t)n * DH + off];
    v.x = fmaxf(v.x, 0.f); v.y = fmaxf(v.y, 0.f);
    v.z = fmaxf(v.z, 0.f); v.w = fmaxf(v.w, 0.f);
    float s = v.x + v.y + v.z + v.w;
    float sq = v.x * v.x + v.y * v.y + v.z * v.z + v.w * v.w;
    #pragma unroll
    for (int o = 16; o > 0; o >>= 1) {
        s  += __shfl_xor_sync(0xffffffffu, s, o);
        sq += __shfl_xor_sync(0xffffffffu, sq, o);
    }
    float mean = s * (1.0f / DH);
    float var = sq * (1.0f / DH) - mean * mean;
    float rstd = rsqrtf(var + 1e-5f);
    float4 gg = *(const float4*)&ln_g[off];
    float4 bb = *(const float4*)&ln_b[off];
    float4 o4;
    o4.x = (v.x - mean) * rstd * gg.x + bb.x;
    o4.y = (v.y - mean) * rstd * gg.y + bb.y;
    o4.z = (v.z - mean) * rstd * gg.z + bb.z;
    o4.w = (v.w - mean) * rstd * gg.w + bb.w;
    *(float4*)&g_h[(size_t)n * DH + off] = o4;
}

// layer 2: emb = u (to d_out), h = relu(u)
__global__ void epi_final(float* __restrict__ out) {
    int warp = threadIdx.x >> 5, lane = threadIdx.x & 31;
    int n = blockIdx.x * 8 + warp;
    if (n >= NN) return;
    int off = lane * 4;
    float4 v = *(const float4*)&g_u[(size_t)n * DH + off];
    *(float4*)&out[(size_t)n * DH + off] = v;
    v.x = fmaxf(v.x, 0.f); v.y = fmaxf(v.y, 0.f);
    v.z = fmaxf(v.z, 0.f); v.w = fmaxf(v.w, 0.f);
    *(float4*)&g_h[(size_t)n * DH + off] = v;
}

// ---------------- pooling + head --------------------------------------------
__global__ void pool_partial() {
    int g = blockIdx.x;
    int chunk = blockIdx.y;
    int f = threadIdx.x;
    int s = g_gstart[g], e = g_gstart[g + 1];
    int len = e - s;
    int per = (len + (int)gridDim.y - 1) / (int)gridDim.y;
    int a = s + chunk * per;
    int b = min(a + per, e);
    float sum = 0.f;
    for (int n = a; n < b; n++) sum += g_h[(size_t)n * DH + f];
    if (a < b) atomicAdd(&g_pool[g * DH + f], sum);
}

__global__ void head_mlp(const float* __restrict__ pw1, const float* __restrict__ pb1,
                         const float* __restrict__ pw2, const float* __restrict__ pb2,
                         float* __restrict__ out) {
    __shared__ float sp[DH];
    __shared__ float sz[DH];
    __shared__ float sl[CC];
    int g = blockIdx.x;
    int f = threadIdx.x;
    float cnt = fmaxf((float)(g_gstart[g + 1] - g_gstart[g]), 1.0f);
    sp[f] = g_pool[g * DH + f] / cnt;
    __syncthreads();
    float z = pb1[f];
    #pragma unroll 8
    for (int k = 0; k < DH; k++) z += sp[k] * pw1[k * DH + f];
    sz[f] = z;
    __syncthreads();
    if (f < CC) {
        float l = pb2[f];
        #pragma unroll 8
        for (int k = 0; k < DH; k++) l += sz[k] * pw2[k * CC + f];
        sl[f] = l;
    }
    __syncthreads();
    if (f < CC) {
        float m = -1e30f;
        #pragma unroll
        for (int c = 0; c < CC; c++) m = fmaxf(m, sl[c]);
        float s = 0.f;
        #pragma unroll
        for (int c = 0; c < CC; c++) s += expf(sl[c] - m);
        out[(size_t)NN * DH + g * CC + f] = sl[f] - m - logf(s);
    }
}

// ---------------- launch ----------------------------------------------------
extern "C" void kernel_launch(void* const* d_in, const int* in_sizes, int n_in,
                              void* d_out, int out_size) {
    const float* x    = (const float*)d_in[0];
    const int* eidx   = (const int*)d_in[1];
    const int* batch  = (const int*)d_in[2];
    const float* w1[3] = {(const float*)d_in[3], (const float*)d_in[7], (const float*)d_in[11]};
    const float* b1[3] = {(const float*)d_in[4], (const float*)d_in[8], (const float*)d_in[12]};
    const float* w2[3] = {(const float*)d_in[5], (const float*)d_in[9], (const float*)d_in[13]};
    const float* b2[3] = {(const float*)d_in[6], (const float*)d_in[10], (const float*)d_in[14]};
    const float* ln_g[2] = {(const float*)d_in[15], (const float*)d_in[17]};
    const float* ln_b[2] = {(const float*)d_in[16], (const float*)d_in[18]};
    const float* pw1 = (const float*)d_in[19];
    const float* pb1 = (const float*)d_in[20];
    const float* pw2 = (const float*)d_in[21];
    const float* pb2 = (const float*)d_in[22];
    float* out = (float*)d_out;

    const int* src = eidx;
    const int* dst = eidx + EE;

    // CSR build (by destination) + graph boundaries
    zero_counts_pool<<<(NN + 255) / 256, 256>>>();
    count_edges<<<(EE + 255) / 256, 256>>>(dst);
    scan_rowptr<<<1, 1024>>>();
    fill_csr<<<(EE + 255) / 256, 256>>>(src, dst);
    graph_bounds<<<1, 96>>>(batch);

    const int gemm_blocks = (NN + 63) / 64;
    const int node_blocks = (NN + 7) / 8;

    for (int L = 0; L < 3; L++) {
        if (L == 0) gather_kernel<true><<<node_blocks, 256>>>(x);
        else        gather_kernel<false><<<node_blocks, 256>>>(nullptr);
        gemm128<0><<<gemm_blocks, 256>>>(w1[L], b1[L]);
        gemm128<1><<<gemm_blocks, 256>>>(w2[L], b2[L]);
        if (L < 2) epi_ln<<<node_blocks, 256>>>(ln_g[L], ln_b[L]);
        else       epi_final<<<node_blocks, 256>>>(out);
    }

    pool_partial<<<dim3(GG, 16), DH>>>();
    head_mlp<<<GG, DH>>>(pw1, pb1, pw2, pb2, out);
}

// round 5
// speedup vs baseline: 1.4599x; 1.4599x over previous
#include <cuda_runtime.h>
#include <cuda_bf16.h>
#include <math.h>
#include <stdint.h>

#define NN 100000
#define EE 1600000
#define DH 128
#define GG 64
#define CC 10
#define NT 782               // ceil(NN/128)
#define NPAD (NT * 128)      // 100096

// ---------------- scratch (static device arrays; allocation forbidden) ------
__device__ float g_t[NPAD * DH];       // t = h + agg  (GEMM1 input)
__device__ float g_hidden[NPAD * DH];  // relu(t@w1+b1)
__device__ float g_h[NPAD * DH];       // LN output / next-layer gather input
__device__ float g_hpool[NPAD * DH];   // relu(u) after layer 2 for pooling
__device__ __nv_bfloat16 g_Wthi[6 * DH * DH];  // weights transposed [n][k], bf16 hi
__device__ __nv_bfloat16 g_Wtlo[6 * DH * DH];  // bf16 lo plane
__device__ int   g_counts[NN];
__device__ int   g_rowptr[NN + 1];
__device__ int   g_cur[NN];
__device__ int   g_csr_src[EE];
__device__ int   g_gstart[GG + 1];
__device__ float g_pool[GG * DH];

// ---------------- helpers ----------------------------------------------------
__device__ __forceinline__ void split2(float a, float b, uint32_t& hw, uint32_t& lw) {
    __nv_bfloat16 ha = __float2bfloat16(a), hb = __float2bfloat16(b);
    float ra = a - __bfloat162float(ha);
    float rb = b - __bfloat162float(hb);
    __nv_bfloat16 la = __float2bfloat16(ra), lb = __float2bfloat16(rb);
    hw = ((uint32_t)__bfloat16_as_ushort(hb) << 16) | __bfloat16_as_ushort(ha);
    lw = ((uint32_t)__bfloat16_as_ushort(lb) << 16) | __bfloat16_as_ushort(la);
}
__device__ __forceinline__ void mma16816(float* c, const uint32_t* a,
                                         uint32_t b0, uint32_t b1) {
    asm("mma.sync.aligned.m16n8k16.row.col.f32.bf16.bf16.f32 "
        "{%0,%1,%2,%3}, {%4,%5,%6,%7}, {%8,%9}, {%0,%1,%2,%3};"
        : "+f"(c[0]), "+f"(c[1]), "+f"(c[2]), "+f"(c[3])
        : "r"(a[0]), "r"(a[1]), "r"(a[2]), "r"(a[3]), "r"(b0), "r"(b1));
}

// ---------------- CSR build --------------------------------------------------
__global__ void zero_counts_pool() {
    int i = blockIdx.x * blockDim.x + threadIdx.x;
    if (i < NN) g_counts[i] = 0;
    if (i < GG * DH) g_pool[i] = 0.0f;
}
__global__ void count_edges(const int* __restrict__ dst) {
    int e = blockIdx.x * blockDim.x + threadIdx.x;
    if (e < EE) atomicAdd(&g_counts[dst[e]], 1);
}
__global__ void scan_rowptr() {
    __shared__ int warp_sums[32];
    __shared__ int s_carry;
    int tid = threadIdx.x;
    int lane = tid & 31, w = tid >> 5;
    if (tid == 0) s_carry = 0;
    __syncthreads();
    for (int base = 0; base < NN; base += 1024) {
        int i = base + tid;
        int v = (i < NN) ? g_counts[i] : 0;
        int incl = v;
        #pragma unroll
        for (int o = 1; o < 32; o <<= 1) {
            int t = __shfl_up_sync(0xffffffffu, incl, o);
            if (lane >= o) incl += t;
        }
        if (lane == 31) warp_sums[w] = incl;
        __syncthreads();
        if (w == 0) {
            int s = warp_sums[lane];
            #pragma unroll
            for (int o = 1; o < 32; o <<= 1) {
                int t = __shfl_up_sync(0xffffffffu, s, o);
                if (lane >= o) s += t;
            }
            warp_sums[lane] = s;
        }
        __syncthreads();
        int woff = (w > 0) ? warp_sums[w - 1] : 0;
        int excl = s_carry + woff + incl - v;
        if (i < NN) { g_rowptr[i] = excl; g_cur[i] = excl; }
        __syncthreads();
        if (tid == 0) s_carry += warp_sums[31];
        __syncthreads();
    }
    if (threadIdx.x == 0) g_rowptr[NN] = s_carry;
}
__global__ void fill_csr(const int* __restrict__ src, const int* __restrict__ dst) {
    int e = blockIdx.x * blockDim.x + threadIdx.x;
    if (e < EE) {
        int p = atomicAdd(&g_cur[dst[e]], 1);
        g_csr_src[p] = src[e];
    }
}
__global__ void graph_bounds(const int* __restrict__ batch) {
    int g = threadIdx.x;
    if (g > GG) return;
    int lo = 0, hi = NN;
    while (lo < hi) {
        int mid = (lo + hi) >> 1;
        if (batch[mid] < g) lo = mid + 1; else hi = mid;
    }
    g_gstart[g] = lo;
}

// ---------------- weight convert: w[k][n] -> Wt[n][k] bf16 hi/lo -------------
__global__ void wconvert(const float* w0, const float* w1, const float* w2,
                         const float* w3, const float* w4, const float* w5) {
    const float* ws[6] = {w0, w1, w2, w3, w4, w5};
    int widx = blockIdx.x >> 2, part = blockIdx.x & 3;
    const float* w = ws[widx];
    __nv_bfloat16* hb = g_Wthi + widx * DH * DH;
    __nv_bfloat16* lb = g_Wtlo + widx * DH * DH;
    int end = (part + 1) * 4096;
    for (int idx = part * 4096 + threadIdx.x; idx < end; idx += 256) {
        int n = idx >> 7, k = idx & 127;
        float v = w[k * DH + n];
        __nv_bfloat16 hi = __float2bfloat16(v);
        __nv_bfloat16 lo = __float2bfloat16(v - __bfloat162float(hi));
        hb[idx] = hi;
        lb[idx] = lo;
    }
}

// ---------------- gather: t[n] = h[n] + sum_{src} h[src] --------------------
template <bool FIRST>
__global__ void gather_kernel(const float* __restrict__ x) {
    const float* __restrict__ h = FIRST ? x : (const float*)g_h;
    int warp = threadIdx.x >> 5, lane = threadIdx.x & 31;
    int n = blockIdx.x * 8 + warp;
    if (n >= NN) return;
    int off = lane * 4;
    float4 acc = *(const float4*)&h[(size_t)n * DH + off];
    int p = g_rowptr[n], e = g_rowptr[n + 1];
    for (; p + 4 <= e; p += 4) {
        int s0 = g_csr_src[p], s1 = g_csr_src[p + 1];
        int s2 = g_csr_src[p + 2], s3 = g_csr_src[p + 3];
        float4 v0 = *(const float4*)&h[(size_t)s0 * DH + off];
        float4 v1 = *(const float4*)&h[(size_t)s1 * DH + off];
        float4 v2 = *(const float4*)&h[(size_t)s2 * DH + off];
        float4 v3 = *(const float4*)&h[(size_t)s3 * DH + off];
        acc.x += v0.x + v1.x + v2.x + v3.x;
        acc.y += v0.y + v1.y + v2.y + v3.y;
        acc.z += v0.z + v1.z + v2.z + v3.z;
        acc.w += v0.w + v1.w + v2.w + v3.w;
    }
    for (; p < e; ++p) {
        int s = g_csr_src[p];
        float4 v = *(const float4*)&h[(size_t)s * DH + off];
        acc.x += v.x; acc.y += v.y; acc.z += v.z; acc.w += v.w;
    }
    *(float4*)&g_t[(size_t)n * DH + off] = acc;
}

// ---------------- HMMA split GEMM kernel -------------------------------------
// C = A @ W + bias, 128x128 tile per block, bf16 hi/lo 3-pass split.
// PHASE 1: A=g_t -> relu -> g_hidden
// PHASE 2, VAR 0: A=g_hidden -> relu -> LN -> g_h
// PHASE 2, VAR 1: A=g_hidden -> u -> out(emb); relu(u) -> g_hpool
#define SA_HI 0
#define SA_LO 34816
#define SW_HI 69632
#define SW_LO 104448
#define SEPI  139264
#define SMEM_DYN (139264 + 640 * 4)
#define PITCHW 68   // smem row pitch in 32-bit words (136 bf16)

template <int PHASE, int VAR>
__global__ void __launch_bounds__(256, 1)
hmma_kernel(int widx, const float* __restrict__ bias,
            const float* __restrict__ lng, const float* __restrict__ lnb,
            float* __restrict__ out) {
    extern __shared__ char smem[];
    uint32_t* sah = (uint32_t*)(smem + SA_HI);
    uint32_t* sal = (uint32_t*)(smem + SA_LO);
    uint32_t* swh = (uint32_t*)(smem + SW_HI);
    uint32_t* swl = (uint32_t*)(smem + SW_LO);
    float* rowsum = (float*)(smem + SEPI);
    float* rowsq  = rowsum + 128;
    float* sb     = rowsum + 256;
    float* slg    = rowsum + 384;
    float* slb    = rowsum + 512;

    int tid = threadIdx.x;
    int tile = blockIdx.x;

    // ---- load A (fp32 -> bf16 hi/lo planes) ----
    {
        const float* Asrc = ((PHASE == 1) ? (const float*)g_t : (const float*)g_hidden)
                            + (size_t)tile * 128 * DH;
        for (int i = tid; i < 4096; i += 256) {       // 128 rows x 32 float4
            int row = i >> 5, c4 = (i & 31) * 4;
            float4 v = *(const float4*)(Asrc + row * DH + c4);
            uint32_t hw0, lw0, hw1, lw1;
            split2(v.x, v.y, hw0, lw0);
            split2(v.z, v.w, hw1, lw1);
            int w = row * PITCHW + (c4 >> 1);
            sah[w] = hw0; sah[w + 1] = hw1;
            sal[w] = lw0; sal[w + 1] = lw1;
        }
        const uint32_t* wh = (const uint32_t*)g_Wthi + widx * 8192;
        const uint32_t* wl = (const uint32_t*)g_Wtlo + widx * 8192;
        for (int i = tid; i < 8192; i += 256) {       // 128 rows x 64 words
            int row = i >> 6, c = i & 63;
            swh[row * PITCHW + c] = wh[i];
            swl[row * PITCHW + c] = wl[i];
        }
        if (tid < 128) {
            sb[tid] = bias[tid];
            if (PHASE == 2 && VAR == 0) {
                slg[tid] = lng[tid];
                slb[tid] = lnb[tid];
                rowsum[tid] = 0.0f;
                rowsq[tid] = 0.0f;
            }
        }
    }
    __syncthreads();

    // ---- compute ----
    int wid = tid >> 5, lane = tid & 31, g = lane >> 2, t = lane & 3;
    int m0 = (wid >> 1) * 32;       // warp row base (2 m16 tiles)
    int nb = (wid & 1) * 64;        // warp col base (8 n8 tiles)

    float acc[2][8][4];
    #pragma unroll
    for (int mi = 0; mi < 2; mi++)
        #pragma unroll
        for (int j = 0; j < 8; j++)
            #pragma unroll
            for (int q = 0; q < 4; q++) acc[mi][j][q] = 0.0f;

    #pragma unroll 1
    for (int pass = 0; pass < 3; pass++) {
        const uint32_t* Ap = (pass == 1) ? sal : sah;
        const uint32_t* Wp = (pass == 2) ? swl : swh;
        #pragma unroll
        for (int kk = 0; kk < 8; kk++) {
            int ko = kk * 8 + t;                        // 32-bit word col
            uint32_t a[2][4];
            #pragma unroll
            for (int mi = 0; mi < 2; mi++) {
                int r = m0 + mi * 16 + g;
                a[mi][0] = Ap[r * PITCHW + ko];
                a[mi][1] = Ap[(r + 8) * PITCHW + ko];
                a[mi][2] = Ap[r * PITCHW + ko + 4];
                a[mi][3] = Ap[(r + 8) * PITCHW + ko + 4];
            }
            #pragma unroll
            for (int j = 0; j < 8; j++) {
                int n = nb + j * 8 + g;
                uint32_t b0 = Wp[n * PITCHW + ko];
                uint32_t b1 = Wp[n * PITCHW + ko + 4];
                mma16816(acc[0][j], a[0], b0, b1);
                mma16816(acc[1][j], a[1], b0, b1);
            }
        }
    }

    // ---- epilogue ----
    if (PHASE == 1) {
        #pragma unroll
        for (int mi = 0; mi < 2; mi++) {
            size_t r0 = (size_t)tile * 128 + m0 + mi * 16 + g;
            #pragma unroll
            for (int j = 0; j < 8; j++) {
                int c = nb + j * 8 + t * 2;
                float2 v0, v1;
                v0.x = fmaxf(acc[mi][j][0] + sb[c], 0.f);
                v0.y = fmaxf(acc[mi][j][1] + sb[c + 1], 0.f);
                v1.x = fmaxf(acc[mi][j][2] + sb[c], 0.f);
                v1.y = fmaxf(acc[mi][j][3] + sb[c + 1], 0.f);
                *(float2*)&g_hidden[r0 * DH + c] = v0;
                *(float2*)&g_hidden[(r0 + 8) * DH + c] = v1;
            }
        }
    } else if (VAR == 0) {
        // relu in place + row partial sums
        float s[2][2], q[2][2];
        #pragma unroll
        for (int mi = 0; mi < 2; mi++) { s[mi][0]=s[mi][1]=q[mi][0]=q[mi][1]=0.f; }
        #pragma unroll
        for (int mi = 0; mi < 2; mi++)
            #pragma unroll
            for (int j = 0; j < 8; j++) {
                int c = nb + j * 8 + t * 2;
                float v0 = fmaxf(acc[mi][j][0] + sb[c], 0.f);
                float v1 = fmaxf(acc[mi][j][1] + sb[c + 1], 0.f);
                float v2 = fmaxf(acc[mi][j][2] + sb[c], 0.f);
                float v3 = fmaxf(acc[mi][j][3] + sb[c + 1], 0.f);
                acc[mi][j][0] = v0; acc[mi][j][1] = v1;
                acc[mi][j][2] = v2; acc[mi][j][3] = v3;
                s[mi][0] += v0 + v1;  q[mi][0] += v0 * v0 + v1 * v1;
                s[mi][1] += v2 + v3;  q[mi][1] += v2 * v2 + v3 * v3;
            }
        #pragma unroll
        for (int mi = 0; mi < 2; mi++)
            #pragma unroll
            for (int rh = 0; rh < 2; rh++) {
                float ss = s[mi][rh], qq = q[mi][rh];
                ss += __shfl_xor_sync(0xffffffffu, ss, 1);
                qq += __shfl_xor_sync(0xffffffffu, qq, 1);
                ss += __shfl_xor_sync(0xffffffffu, ss, 2);
                qq += __shfl_xor_sync(0xffffffffu, qq, 2);
                if (t == 0) {
                    int rl = m0 + mi * 16 + rh * 8 + g;
                    atomicAdd(&rowsum[rl], ss);
                    atomicAdd(&rowsq[rl], qq);
                }
            }
        __syncthreads();
        if (tid < 128) {
            float mean = rowsum[tid] * (1.0f / DH);
            float var = rowsq[tid] * (1.0f / DH) - mean * mean;
            rowsum[tid] = mean;
            rowsq[tid] = rsqrtf(var + 1e-5f);
        }
        __syncthreads();
        #pragma unroll
        for (int mi = 0; mi < 2; mi++)
            #pragma unroll
            for (int rh = 0; rh < 2; rh++) {
                int rl = m0 + mi * 16 + rh * 8 + g;
                float mean = rowsum[rl], rs = rowsq[rl];
                size_t row = (size_t)tile * 128 + rl;
                #pragma unroll
                for (int j = 0; j < 8; j++) {
                    int c = nb + j * 8 + t * 2;
                    float v0 = acc[mi][j][rh * 2];
                    float v1 = acc[mi][j][rh * 2 + 1];
                    float2 o;
                    o.x = (v0 - mean) * rs * slg[c] + slb[c];
                    o.y = (v1 - mean) * rs * slg[c + 1] + slb[c + 1];
                    *(float2*)&g_h[row * DH + c] = o;
                }
            }
    } else {
        #pragma unroll
        for (int mi = 0; mi < 2; mi++)
            #pragma unroll
            for (int rh = 0; rh < 2; rh++) {
                size_t row = (size_t)tile * 128 + m0 + mi * 16 + rh * 8 + g;
                if (row < NN) {
                    #pragma unroll
                    for (int j = 0; j < 8; j++) {
                        int c = nb + j * 8 + t * 2;
                        float2 u;
                        u.x = acc[mi][j][rh * 2] + sb[c];
                        u.y = acc[mi][j][rh * 2 + 1] + sb[c + 1];
                        *(float2*)&out[row * DH + c] = u;
                        u.x = fmaxf(u.x, 0.f);
                        u.y = fmaxf(u.y, 0.f);
                        *(float2*)&g_hpool[row * DH + c] = u;
                    }
                }
            }
    }
}

// ---------------- pooling + head --------------------------------------------
__global__ void pool_partial() {
    int g = blockIdx.x;
    int chunk = blockIdx.y;
    int f = threadIdx.x;
    int s = g_gstart[g], e = g_gstart[g + 1];
    int len = e - s;
    int per = (len + (int)gridDim.y - 1) / (int)gridDim.y;
    int a = s + chunk * per;
    int b = min(a + per, e);
    float sum = 0.f;
    for (int n = a; n < b; n++) sum += g_hpool[(size_t)n * DH + f];
    if (a < b) atomicAdd(&g_pool[g * DH + f], sum);
}

__global__ void head_mlp(const float* __restrict__ pw1, const float* __restrict__ pb1,
                         const float* __restrict__ pw2, const float* __restrict__ pb2,
                         float* __restrict__ out) {
    __shared__ float sp[DH];
    __shared__ float sz[DH];
    __shared__ float sl[CC];
    int g = blockIdx.x;
    int f = threadIdx.x;
    float cnt = fmaxf((float)(g_gstart[g + 1] - g_gstart[g]), 1.0f);
    sp[f] = g_pool[g * DH + f] / cnt;
    __syncthreads();
    float z = pb1[f];
    #pragma unroll 8
    for (int k = 0; k < DH; k++) z += sp[k] * pw1[k * DH + f];
    sz[f] = z;
    __syncthreads();
    if (f < CC) {
        float l = pb2[f];
        #pragma unroll 8
        for (int k = 0; k < DH; k++) l += sz[k] * pw2[k * CC + f];
        sl[f] = l;
    }
    __syncthreads();
    if (f < CC) {
        float m = -1e30f;
        #pragma unroll
        for (int c = 0; c < CC; c++) m = fmaxf(m, sl[c]);
        float s = 0.f;
        #pragma unroll
        for (int c = 0; c < CC; c++) s += expf(sl[c] - m);
        out[(size_t)NN * DH + g * CC + f] = sl[f] - m - logf(s);
    }
}

// ---------------- launch ----------------------------------------------------
extern "C" void kernel_launch(void* const* d_in, const int* in_sizes, int n_in,
                              void* d_out, int out_size) {
    const float* x    = (const float*)d_in[0];
    const int* eidx   = (const int*)d_in[1];
    const int* batch  = (const int*)d_in[2];
    const float* w1[3] = {(const float*)d_in[3], (const float*)d_in[7], (const float*)d_in[11]};
    const float* b1[3] = {(const float*)d_in[4], (const float*)d_in[8], (const float*)d_in[12]};
    const float* w2[3] = {(const float*)d_in[5], (const float*)d_in[9], (const float*)d_in[13]};
    const float* b2[3] = {(const float*)d_in[6], (const float*)d_in[10], (const float*)d_in[14]};
    const float* ln_g[2] = {(const float*)d_in[15], (const float*)d_in[17]};
    const float* ln_b[2] = {(const float*)d_in[16], (const float*)d_in[18]};
    const float* pw1 = (const float*)d_in[19];
    const float* pb1 = (const float*)d_in[20];
    const float* pw2 = (const float*)d_in[21];
    const float* pb2 = (const float*)d_in[22];
    float* out = (float*)d_out;

    static bool attr_done = false;
    if (!attr_done) {
        cudaFuncSetAttribute((const void*)hmma_kernel<1, 0>,
                             cudaFuncAttributeMaxDynamicSharedMemorySize, SMEM_DYN);
        cudaFuncSetAttribute((const void*)hmma_kernel<2, 0>,
                             cudaFuncAttributeMaxDynamicSharedMemorySize, SMEM_DYN);
        cudaFuncSetAttribute((const void*)hmma_kernel<2, 1>,
                             cudaFuncAttributeMaxDynamicSharedMemorySize, SMEM_DYN);
        attr_done = true;
    }

    const int* src = eidx;
    const int* dst = eidx + EE;

    wconvert<<<24, 256>>>(w1[0], w2[0], w1[1], w2[1], w1[2], w2[2]);
    zero_counts_pool<<<(NN + 255) / 256, 256>>>();
    count_edges<<<(EE + 255) / 256, 256>>>(dst);
    scan_rowptr<<<1, 1024>>>();
    fill_csr<<<(EE + 255) / 256, 256>>>(src, dst);
    graph_bounds<<<1, 96>>>(batch);

    const int node_blocks = (NN + 7) / 8;

    for (int L = 0; L < 3; L++) {
        if (L == 0) gather_kernel<true><<<node_blocks, 256>>>(x);
        else        gather_kernel<false><<<node_blocks, 256>>>(nullptr);
        hmma_kernel<1, 0><<<NT, 256, SMEM_DYN>>>(2 * L, b1[L], nullptr, nullptr, nullptr);
        if (L < 2)
            hmma_kernel<2, 0><<<NT, 256, SMEM_DYN>>>(2 * L + 1, b2[L], ln_g[L], ln_b[L], nullptr);
        else
            hmma_kernel<2, 1><<<NT, 256, SMEM_DYN>>>(2 * L + 1, b2[L], nullptr, nullptr, out);
    }

    pool_partial<<<dim3(GG, 16), DH>>>();
    head_mlp<<<GG, DH>>>(pw1, pb1, pw2, pb2, out);
}

// round 6
// speedup vs baseline: 2.1965x; 1.5045x over previous
#include <cuda_runtime.h>
#include <cuda_bf16.h>
#include <math.h>
#include <stdint.h>

#define NN 100000
#define EE 1600000
#define DH 128
#define GG 64
#define CC 10
#define NT 782               // ceil(NN/128)
#define NPAD (NT * 128)      // 100096
#define SCB 98               // scan blocks: ceil(NN/1024)

// ---------------- scratch (static device arrays; allocation forbidden) ------
__device__ float g_t[NPAD * DH];       // t = h + agg  (GEMM1 input)
__device__ float g_hidden[NPAD * DH];  // relu(t@w1+b1)
__device__ float g_h[NPAD * DH];       // LN output / next-layer gather input
__device__ float g_hpool[NPAD * DH];   // relu(u) after layer 2 for pooling
__device__ __nv_bfloat16 g_Wthi[6 * DH * DH];  // weights transposed [n][k], bf16 hi
__device__ __nv_bfloat16 g_Wtlo[6 * DH * DH];  // bf16 lo plane
__device__ int   g_counts[NN];
__device__ int   g_rowptr[NN + 1];
__device__ int   g_cur[NN];
__device__ int   g_csr_src[EE];
__device__ int   g_bsum[SCB];
__device__ int   g_boff[SCB];
__device__ int   g_gstart[GG + 1];
__device__ float g_pool[GG * DH];

// ---------------- helpers ----------------------------------------------------
__device__ __forceinline__ void split2(float a, float b, uint32_t& hw, uint32_t& lw) {
    __nv_bfloat16 ha = __float2bfloat16(a), hb = __float2bfloat16(b);
    float ra = a - __bfloat162float(ha);
    float rb = b - __bfloat162float(hb);
    __nv_bfloat16 la = __float2bfloat16(ra), lb = __float2bfloat16(rb);
    hw = ((uint32_t)__bfloat16_as_ushort(hb) << 16) | __bfloat16_as_ushort(ha);
    lw = ((uint32_t)__bfloat16_as_ushort(lb) << 16) | __bfloat16_as_ushort(la);
}
__device__ __forceinline__ void mma16816(float* c, const uint32_t* a,
                                         uint32_t b0, uint32_t b1) {
    asm("mma.sync.aligned.m16n8k16.row.col.f32.bf16.bf16.f32 "
        "{%0,%1,%2,%3}, {%4,%5,%6,%7}, {%8,%9}, {%0,%1,%2,%3};"
        : "+f"(c[0]), "+f"(c[1]), "+f"(c[2]), "+f"(c[3])
        : "r"(a[0]), "r"(a[1]), "r"(a[2]), "r"(a[3]), "r"(b0), "r"(b1));
}
__device__ __forceinline__ void cp_async16(uint32_t smem_dst, const void* gsrc) {
    asm volatile("cp.async.cg.shared.global [%0], [%1], 16;"
                 :: "r"(smem_dst), "l"(gsrc));
}
__device__ __forceinline__ void cp_async_commit_wait_all() {
    asm volatile("cp.async.commit_group;\n\tcp.async.wait_group 0;" ::: "memory");
}
__device__ __forceinline__ uint32_t smem_u32(const void* p) {
    uint32_t a;
    asm("{ .reg .u64 t; cvta.to.shared.u64 t, %1; cvt.u32.u64 %0, t; }" : "=r"(a) : "l"(p));
    return a;
}

// ---------------- prep: weight convert + zero counts/pool --------------------
// blocks 0..23: weight convert (widx = b>>2, quarter = b&3)
// block 24: zero pool; blocks 25..123: zero counts
__global__ void prep_kernel(const float* w0, const float* w1, const float* w2,
                            const float* w3, const float* w4, const float* w5) {
    int b = blockIdx.x;
    if (b < 24) {
        const float* ws[6] = {w0, w1, w2, w3, w4, w5};
        int widx = b >> 2, part = b & 3;
        const float* w = ws[widx];
        __nv_bfloat16* hb = g_Wthi + widx * DH * DH;
        __nv_bfloat16* lb = g_Wtlo + widx * DH * DH;
        int end = (part + 1) * 4096;
        for (int idx = part * 4096 + threadIdx.x; idx < end; idx += 256) {
            int n = idx >> 7, k = idx & 127;
            float v = w[k * DH + n];
            __nv_bfloat16 hi = __float2bfloat16(v);
            __nv_bfloat16 lo = __float2bfloat16(v - __bfloat162float(hi));
            hb[idx] = hi;
            lb[idx] = lo;
        }
    } else if (b == 24) {
        for (int i = threadIdx.x; i < GG * DH; i += 256) g_pool[i] = 0.0f;
    } else {
        int i = (b - 25) * 1024 + threadIdx.x;
        #pragma unroll
        for (int q = 0; q < 4; q++) {
            int j = i + q * 256;
            if (j < NN) g_counts[j] = 0;
        }
    }
}

__global__ void count_edges(const int* __restrict__ dst) {
    int e = blockIdx.x * blockDim.x + threadIdx.x;
    if (e < EE) atomicAdd(&g_counts[dst[e]], 1);
}

// ---------------- parallel scan (3 stages) ----------------------------------
__global__ void scan_stage1() {
    __shared__ int wsum[32];
    int tid = threadIdx.x, lane = tid & 31, w = tid >> 5;
    int i = blockIdx.x * 1024 + tid;
    int v = (i < NN) ? g_counts[i] : 0;
    int s = v;
    #pragma unroll
    for (int o = 1; o < 32; o <<= 1) s += __shfl_xor_sync(0xffffffffu, s, o);
    if (lane == 0) wsum[w] = s;
    __syncthreads();
    if (w == 0) {
        int t = (lane < 32) ? wsum[lane] : 0;
        #pragma unroll
        for (int o = 1; o < 32; o <<= 1) t += __shfl_xor_sync(0xffffffffu, t, o);
        if (lane == 0) g_bsum[blockIdx.x] = t;
    }
}
// single block: exclusive scan of SCB block sums + graph bounds binary search
__global__ void scan_stage2(const int* __restrict__ batch) {
    int tid = threadIdx.x, lane = tid & 31, w = tid >> 5;
    __shared__ int wsum[4];
    if (tid < 128) {
        int v = (tid < SCB) ? g_bsum[tid] : 0;
        int incl = v;
        #pragma unroll
        for (int o = 1; o < 32; o <<= 1) {
            int t = __shfl_up_sync(0xffffffffu, incl, o);
            if (lane >= o) incl += t;
        }
        if (lane == 31) wsum[w] = incl;
        __syncthreads();
        int woff = 0;
        #pragma unroll
        for (int q = 0; q < 4; q++) if (q < w) woff += wsum[q];
        if (tid < SCB) g_boff[tid] = woff + incl - v;
        if (tid == SCB - 1) g_rowptr[NN] = woff + incl;
    } else {
        __syncthreads();
        int g = tid - 128;          // 128..255 -> graphs 0..127 (need 0..64)
        if (g <= GG) {
            int lo = 0, hi = NN;
            while (lo < hi) {
                int mid = (lo + hi) >> 1;
                if (batch[mid] < g) lo = mid + 1; else hi = mid;
            }
            g_gstart[g] = lo;
        }
    }
}
__global__ void scan_stage3() {
    __shared__ int wsum[32];
    int tid = threadIdx.x, lane = tid & 31, w = tid >> 5;
    int i = blockIdx.x * 1024 + tid;
    int v = (i < NN) ? g_counts[i] : 0;
    int incl = v;
    #pragma unroll
    for (int o = 1; o < 32; o <<= 1) {
        int t = __shfl_up_sync(0xffffffffu, incl, o);
        if (lane >= o) incl += t;
    }
    if (lane == 31) wsum[w] = incl;
    __syncthreads();
    if (w == 0) {
        int s = wsum[lane];
        #pragma unroll
        for (int o = 1; o < 32; o <<= 1) {
            int t = __shfl_up_sync(0xffffffffu, s, o);
            if (lane >= o) s += t;
        }
        wsum[lane] = s;
    }
    __syncthreads();
    if (i < NN) {
        int woff = (w > 0) ? wsum[w - 1] : 0;
        int excl = g_boff[blockIdx.x] + woff + incl - v;
        g_rowptr[i] = excl;
        g_cur[i] = excl;
    }
}

__global__ void fill_csr(const int* __restrict__ src, const int* __restrict__ dst) {
    int e = blockIdx.x * blockDim.x + threadIdx.x;
    if (e < EE) {
        int p = atomicAdd(&g_cur[dst[e]], 1);
        g_csr_src[p] = src[e];
    }
}

// ---------------- gather: t[n] = h[n] + sum_{src} h[src] --------------------
template <bool FIRST>
__global__ void gather_kernel(const float* __restrict__ x) {
    const float* __restrict__ h = FIRST ? x : (const float*)g_h;
    int warp = threadIdx.x >> 5, lane = threadIdx.x & 31;
    int n = blockIdx.x * 8 + warp;
    if (n >= NN) return;
    int off = lane * 4;
    float4 acc = *(const float4*)&h[(size_t)n * DH + off];
    int p = g_rowptr[n], e = g_rowptr[n + 1];
    for (; p + 4 <= e; p += 4) {
        int s0 = g_csr_src[p], s1 = g_csr_src[p + 1];
        int s2 = g_csr_src[p + 2], s3 = g_csr_src[p + 3];
        float4 v0 = *(const float4*)&h[(size_t)s0 * DH + off];
        float4 v1 = *(const float4*)&h[(size_t)s1 * DH + off];
        float4 v2 = *(const float4*)&h[(size_t)s2 * DH + off];
        float4 v3 = *(const float4*)&h[(size_t)s3 * DH + off];
        acc.x += v0.x + v1.x + v2.x + v3.x;
        acc.y += v0.y + v1.y + v2.y + v3.y;
        acc.z += v0.z + v1.z + v2.z + v3.z;
        acc.w += v0.w + v1.w + v2.w + v3.w;
    }
    for (; p < e; ++p) {
        int s = g_csr_src[p];
        float4 v = *(const float4*)&h[(size_t)s * DH + off];
        acc.x += v.x; acc.y += v.y; acc.z += v.z; acc.w += v.w;
    }
    *(float4*)&g_t[(size_t)n * DH + off] = acc;
}

// ---------------- HMMA split GEMM kernel -------------------------------------
// C = A @ W + bias, 128x128 tile per block, bf16 hi/lo 3-pass split.
// PHASE 1: A=g_t -> relu -> g_hidden
// PHASE 2, VAR 0: A=g_hidden -> relu -> LN -> g_h
// PHASE 2, VAR 1: A=g_hidden -> u -> out(emb); relu(u) -> g_hpool
#define SA_F32 0                       // staging: A fp32 (68KB used transiently)
#define SA_HI 0
#define SA_LO 34816
#define SW_HI 69632
#define SW_LO 104448
#define SEPI  139264
#define SMEM_DYN (139264 + 640 * 4 + 1024)
#define PITCHW 68   // smem row pitch in 32-bit words (136 bf16)

template <int PHASE, int VAR>
__global__ void __launch_bounds__(256, 1)
hmma_kernel(int widx, const float* __restrict__ bias,
            const float* __restrict__ lng, const float* __restrict__ lnb,
            float* __restrict__ out) {
    extern __shared__ char smem[];
    uint32_t* sah = (uint32_t*)(smem + SA_HI);
    uint32_t* sal = (uint32_t*)(smem + SA_LO);
    uint32_t* swh = (uint32_t*)(smem + SW_HI);
    uint32_t* swl = (uint32_t*)(smem + SW_LO);
    float* rowsum = (float*)(smem + SEPI);
    float* rowsq  = rowsum + 128;
    float* sb     = rowsum + 256;
    float* slg    = rowsum + 384;
    float* slb    = rowsum + 512;

    int tid = threadIdx.x;
    int tile = blockIdx.x;

    // ---- async-load W planes directly (bf16, same layout transform) ----
    {
        // W rows are 64 words = 256B; copy with cp.async 16B chunks into pitched rows.
        const char* wh = (const char*)((const uint32_t*)g_Wthi + widx * 8192);
        const char* wl = (const char*)((const uint32_t*)g_Wtlo + widx * 8192);
        uint32_t swh_b = smem_u32(swh), swl_b = smem_u32(swl);
        for (int i = tid; i < 2048; i += 256) {      // 128 rows x 16 chunks of 16B
            int row = i >> 4, c16 = i & 15;
            uint32_t doff = (row * PITCHW + c16 * 4) * 4;
            cp_async16(swh_b + doff, wh + i * 16);
            cp_async16(swl_b + doff, wl + i * 16);
        }
    }
    // ---- load A (fp32 -> bf16 hi/lo planes in registers -> smem) ----
    {
        const float* Asrc = ((PHASE == 1) ? (const float*)g_t : (const float*)g_hidden)
                            + (size_t)tile * 128 * DH;
        #pragma unroll
        for (int q = 0; q < 16; q++) {               // 4096 float4s / 256 threads
            int i = q * 256 + tid;
            int row = i >> 5, c4 = (i & 31) * 4;
            float4 v = *(const float4*)(Asrc + row * DH + c4);
            uint32_t hw0, lw0, hw1, lw1;
            split2(v.x, v.y, hw0, lw0);
            split2(v.z, v.w, hw1, lw1);
            int w = row * PITCHW + (c4 >> 1);
            sah[w] = hw0; sah[w + 1] = hw1;
            sal[w] = lw0; sal[w + 1] = lw1;
        }
        if (tid < 128) {
            sb[tid] = bias[tid];
            if (PHASE == 2 && VAR == 0) {
                slg[tid] = lng[tid];
                slb[tid] = lnb[tid];
                rowsum[tid] = 0.0f;
                rowsq[tid] = 0.0f;
            }
        }
    }
    cp_async_commit_wait_all();
    __syncthreads();

    // ---- compute ----
    int wid = tid >> 5, lane = tid & 31, g = lane >> 2, t = lane & 3;
    int m0 = (wid >> 1) * 32;       // warp row base (2 m16 tiles)
    int nb = (wid & 1) * 64;        // warp col base (8 n8 tiles)

    float acc[2][8][4];
    #pragma unroll
    for (int mi = 0; mi < 2; mi++)
        #pragma unroll
        for (int j = 0; j < 8; j++)
            #pragma unroll
            for (int q = 0; q < 4; q++) acc[mi][j][q] = 0.0f;

    #pragma unroll 1
    for (int pass = 0; pass < 3; pass++) {
        const uint32_t* Ap = (pass == 1) ? sal : sah;
        const uint32_t* Wp = (pass == 2) ? swl : swh;
        #pragma unroll
        for (int kk = 0; kk < 8; kk++) {
            int ko = kk * 8 + t;                        // 32-bit word col
            uint32_t a[2][4];
            #pragma unroll
            for (int mi = 0; mi < 2; mi++) {
                int r = m0 + mi * 16 + g;
                a[mi][0] = Ap[r * PITCHW + ko];
                a[mi][1] = Ap[(r + 8) * PITCHW + ko];
                a[mi][2] = Ap[r * PITCHW + ko + 4];
                a[mi][3] = Ap[(r + 8) * PITCHW + ko + 4];
            }
            #pragma unroll
            for (int j = 0; j < 8; j++) {
                int n = nb + j * 8 + g;
                uint32_t b0 = Wp[n * PITCHW + ko];
                uint32_t b1 = Wp[n * PITCHW + ko + 4];
                mma16816(acc[0][j], a[0], b0, b1);
                mma16816(acc[1][j], a[1], b0, b1);
            }
        }
    }

    // ---- epilogue ----
    if (PHASE == 1) {
        #pragma unroll
        for (int mi = 0; mi < 2; mi++) {
            size_t r0 = (size_t)tile * 128 + m0 + mi * 16 + g;
            #pragma unroll
            for (int j = 0; j < 8; j++) {
                int c = nb + j * 8 + t * 2;
                float2 v0, v1;
                v0.x = fmaxf(acc[mi][j][0] + sb[c], 0.f);
                v0.y = fmaxf(acc[mi][j][1] + sb[c + 1], 0.f);
                v1.x = fmaxf(acc[mi][j][2] + sb[c], 0.f);
                v1.y = fmaxf(acc[mi][j][3] + sb[c + 1], 0.f);
                *(float2*)&g_hidden[r0 * DH + c] = v0;
                *(float2*)&g_hidden[(r0 + 8) * DH + c] = v1;
            }
        }
    } else if (VAR == 0) {
        float s[2][2], q[2][2];
        #pragma unroll
        for (int mi = 0; mi < 2; mi++) { s[mi][0]=s[mi][1]=q[mi][0]=q[mi][1]=0.f; }
        #pragma unroll
        for (int mi = 0; mi < 2; mi++)
            #pragma unroll
            for (int j = 0; j < 8; j++) {
                int c = nb + j * 8 + t * 2;
                float v0 = fmaxf(acc[mi][j][0] + sb[c], 0.f);
                float v1 = fmaxf(acc[mi][j][1] + sb[c + 1], 0.f);
                float v2 = fmaxf(acc[mi][j][2] + sb[c], 0.f);
                float v3 = fmaxf(acc[mi][j][3] + sb[c + 1], 0.f);
                acc[mi][j][0] = v0; acc[mi][j][1] = v1;
                acc[mi][j][2] = v2; acc[mi][j][3] = v3;
                s[mi][0] += v0 + v1;  q[mi][0] += v0 * v0 + v1 * v1;
                s[mi][1] += v2 + v3;  q[mi][1] += v2 * v2 + v3 * v3;
            }
        #pragma unroll
        for (int mi = 0; mi < 2; mi++)
            #pragma unroll
            for (int rh = 0; rh < 2; rh++) {
                float ss = s[mi][rh], qq = q[mi][rh];
                ss += __shfl_xor_sync(0xffffffffu, ss, 1);
                qq += __shfl_xor_sync(0xffffffffu, qq, 1);
                ss += __shfl_xor_sync(0xffffffffu, ss, 2);
                qq += __shfl_xor_sync(0xffffffffu, qq, 2);
                if (t == 0) {
                    int rl = m0 + mi * 16 + rh * 8 + g;
                    atomicAdd(&rowsum[rl], ss);
                    atomicAdd(&rowsq[rl], qq);
                }
            }
        __syncthreads();
        if (tid < 128) {
            float mean = rowsum[tid] * (1.0f / DH);
            float var = rowsq[tid] * (1.0f / DH) - mean * mean;
            rowsum[tid] = mean;
            rowsq[tid] = rsqrtf(var + 1e-5f);
        }
        __syncthreads();
        #pragma unroll
        for (int mi = 0; mi < 2; mi++)
            #pragma unroll
            for (int rh = 0; rh < 2; rh++) {
                int rl = m0 + mi * 16 + rh * 8 + g;
                float mean = rowsum[rl], rs = rowsq[rl];
                size_t row = (size_t)tile * 128 + rl;
                #pragma unroll
                for (int j = 0; j < 8; j++) {
                    int c = nb + j * 8 + t * 2;
                    float v0 = acc[mi][j][rh * 2];
                    float v1 = acc[mi][j][rh * 2 + 1];
                    float2 o;
                    o.x = (v0 - mean) * rs * slg[c] + slb[c];
                    o.y = (v1 - mean) * rs * slg[c + 1] + slb[c + 1];
                    *(float2*)&g_h[row * DH + c] = o;
                }
            }
    } else {
        #pragma unroll
        for (int mi = 0; mi < 2; mi++)
            #pragma unroll
            for (int rh = 0; rh < 2; rh++) {
                size_t row = (size_t)tile * 128 + m0 + mi * 16 + rh * 8 + g;
                if (row < NN) {
                    #pragma unroll
                    for (int j = 0; j < 8; j++) {
                        int c = nb + j * 8 + t * 2;
                        float2 u;
                        u.x = acc[mi][j][rh * 2] + sb[c];
                        u.y = acc[mi][j][rh * 2 + 1] + sb[c + 1];
                        *(float2*)&out[row * DH + c] = u;
                        u.x = fmaxf(u.x, 0.f);
                        u.y = fmaxf(u.y, 0.f);
                        *(float2*)&g_hpool[row * DH + c] = u;
                    }
                }
            }
    }
}

// ---------------- pooling + head --------------------------------------------
__global__ void pool_partial() {
    int g = blockIdx.x;
    int chunk = blockIdx.y;
    int f = threadIdx.x;
    int s = g_gstart[g], e = g_gstart[g + 1];
    int len = e - s;
    int per = (len + (int)gridDim.y - 1) / (int)gridDim.y;
    int a = s + chunk * per;
    int b = min(a + per, e);
    float sum = 0.f;
    for (int n = a; n < b; n++) sum += g_hpool[(size_t)n * DH + f];
    if (a < b) atomicAdd(&g_pool[g * DH + f], sum);
}

__global__ void head_mlp(const float* __restrict__ pw1, const float* __restrict__ pb1,
                         const float* __restrict__ pw2, const float* __restrict__ pb2,
                         float* __restrict__ out) {
    __shared__ float sp[DH];
    __shared__ float sz[DH];
    __shared__ float sl[CC];
    int g = blockIdx.x;
    int f = threadIdx.x;
    float cnt = fmaxf((float)(g_gstart[g + 1] - g_gstart[g]), 1.0f);
    sp[f] = g_pool[g * DH + f] / cnt;
    __syncthreads();
    float z = pb1[f];
    #pragma unroll 8
    for (int k = 0; k < DH; k++) z += sp[k] * pw1[k * DH + f];
    sz[f] = z;
    __syncthreads();
    if (f < CC) {
        float l = pb2[f];
        #pragma unroll 8
        for (int k = 0; k < DH; k++) l += sz[k] * pw2[k * CC + f];
        sl[f] = l;
    }
    __syncthreads();
    if (f < CC) {
        float m = -1e30f;
        #pragma unroll
        for (int c = 0; c < CC; c++) m = fmaxf(m, sl[c]);
        float s = 0.f;
        #pragma unroll
        for (int c = 0; c < CC; c++) s += expf(sl[c] - m);
        out[(size_t)NN * DH + g * CC + f] = sl[f] - m - logf(s);
    }
}

// ---------------- launch ----------------------------------------------------
extern "C" void kernel_launch(void* const* d_in, const int* in_sizes, int n_in,
                              void* d_out, int out_size) {
    const float* x    = (const float*)d_in[0];
    const int* eidx   = (const int*)d_in[1];
    const int* batch  = (const int*)d_in[2];
    const float* w1[3] = {(const float*)d_in[3], (const float*)d_in[7], (const float*)d_in[11]};
    const float* b1[3] = {(const float*)d_in[4], (const float*)d_in[8], (const float*)d_in[12]};
    const float* w2[3] = {(const float*)d_in[5], (const float*)d_in[9], (const float*)d_in[13]};
    const float* b2[3] = {(const float*)d_in[6], (const float*)d_in[10], (const float*)d_in[14]};
    const float* ln_g[2] = {(const float*)d_in[15], (const float*)d_in[17]};
    const float* ln_b[2] = {(const float*)d_in[16], (const float*)d_in[18]};
    const float* pw1 = (const float*)d_in[19];
    const float* pb1 = (const float*)d_in[20];
    const float* pw2 = (const float*)d_in[21];
    const float* pb2 = (const float*)d_in[22];
    float* out = (float*)d_out;

    cudaFuncSetAttribute((const void*)hmma_kernel<1, 0>,
                         cudaFuncAttributeMaxDynamicSharedMemorySize, SMEM_DYN);
    cudaFuncSetAttribute((const void*)hmma_kernel<2, 0>,
                         cudaFuncAttributeMaxDynamicSharedMemorySize, SMEM_DYN);
    cudaFuncSetAttribute((const void*)hmma_kernel<2, 1>,
                         cudaFuncAttributeMaxDynamicSharedMemorySize, SMEM_DYN);

    const int* src = eidx;
    const int* dst = eidx + EE;

    prep_kernel<<<25 + SCB, 256>>>(w1[0], w2[0], w1[1], w2[1], w1[2], w2[2]);
    count_edges<<<(EE + 255) / 256, 256>>>(dst);
    scan_stage1<<<SCB, 1024>>>();
    scan_stage2<<<1, 256>>>(batch);
    scan_stage3<<<SCB, 1024>>>();
    fill_csr<<<(EE + 255) / 256, 256>>>(src, dst);

    const int node_blocks = (NN + 7) / 8;

    for (int L = 0; L < 3; L++) {
        if (L == 0) gather_kernel<true><<<node_blocks, 256>>>(x);
        else        gather_kernel<false><<<node_blocks, 256>>>(nullptr);
        hmma_kernel<1, 0><<<NT, 256, SMEM_DYN>>>(2 * L, b1[L], nullptr, nullptr, nullptr);
        if (L < 2)
            hmma_kernel<2, 0><<<NT, 256, SMEM_DYN>>>(2 * L + 1, b2[L], ln_g[L], ln_b[L], nullptr);
        else
            hmma_kernel<2, 1><<<NT, 256, SMEM_DYN>>>(2 * L + 1, b2[L], nullptr, nullptr, out);
    }

    pool_partial<<<dim3(GG, 16), DH>>>();
    head_mlp<<<GG, DH>>>(pw1, pb1, pw2, pb2, out);
}